// round 16
// baseline (speedup 1.0000x reference)
#include <cuda_runtime.h>
#include <cuda_fp16.h>
#include <math_constants.h>
#include <cstdint>

#define BATCH 16
#define NPTS  4096
#define GPTS  1024
#define D1    128
#define D2    256
#define CIN   384
#define CH    256
#define COUT  256
#define NT    (BATCH * NPTS)      /* 65536 flat rows */
#define BN_EPS 1e-5f

#define SROW 40                    /* smem row stride in fp16 (80 B), K-chunk 32 */
#define TILEB (128 * SROW * 2)     /* one tile in bytes (10240) */

// ======================= scratch (device globals) ===========================
__device__ uint4 g_X1[(size_t)NT * CIN / 8];     // fp16 [NT][384]
__device__ uint4 g_X2[(size_t)NT * CH / 8];      // fp16 [NT][256]
__device__ __half g_Y1h[(size_t)NT * CH];         // fp16 [NT][256] raw conv1
__device__ __half g_Y2h[(size_t)NT * COUT];       // fp16 [NT][256] raw conv2
__device__ float g_f2t[(size_t)BATCH * GPTS * D2];
__device__ float4 g_knnw[NT];                     // (w0,w1,w2,-)
__device__ int4   g_knni[NT];                     // (i0,i1,i2,-)
__device__ uint4 g_W1h[CH * CIN / 8];             // fp16 [256][384]
__device__ uint4 g_W2h[COUT * CH / 8];            // fp16 [256][256]
__device__ float g_sum1[CH],   g_sumsq1[CH];
__device__ float g_sum2[COUT], g_sumsq2[COUT];
__device__ float g_scale1[CH],   g_shift1[CH];
__device__ float g_scale2[COUT], g_shift2[COUT];

// ======================= asm helpers ========================================
__device__ __forceinline__ uint32_t smem_u32(const void* p) {
    uint32_t a;
    asm("{ .reg .u64 t; cvta.to.shared.u64 t, %1; cvt.u32.u64 %0, t; }"
        : "=r"(a) : "l"(p));
    return a;
}

#define CPA16(dst_u32, src_ptr) \
    asm volatile("cp.async.cg.shared.global [%0], [%1], 16;" \
                 :: "r"(dst_u32), "l"(src_ptr) : "memory")
#define CP_COMMIT() asm volatile("cp.async.commit_group;" ::: "memory")
#define CP_WAIT1()  asm volatile("cp.async.wait_group 1;" ::: "memory")
#define CP_WAIT0()  asm volatile("cp.async.wait_group 0;" ::: "memory")

__device__ __forceinline__ void mma16816(float c[4],
                                         uint32_t a0, uint32_t a1, uint32_t a2, uint32_t a3,
                                         uint32_t b0, uint32_t b1) {
    asm volatile(
        "mma.sync.aligned.m16n8k16.row.col.f32.f16.f16.f32 "
        "{%0,%1,%2,%3}, {%4,%5,%6,%7}, {%8,%9}, {%0,%1,%2,%3};"
        : "+f"(c[0]), "+f"(c[1]), "+f"(c[2]), "+f"(c[3])
        : "r"(a0), "r"(a1), "r"(a2), "r"(a3), "r"(b0), "r"(b1));
}

// ======================= small kernels ======================================
__global__ void init_kernel() {
    int t = threadIdx.x;
    g_sum1[t] = 0.f; g_sumsq1[t] = 0.f;
    g_sum2[t] = 0.f; g_sumsq2[t] = 0.f;
}

__global__ void convert_w_kernel(const float* __restrict__ W1,
                                 const float* __restrict__ W2) {
    int i = blockIdx.x * blockDim.x + threadIdx.x;
    const int t1 = CH * CIN;
    const int t2 = COUT * CH;
    if (i < t1) {
        ((__half*)g_W1h)[i] = __float2half(W1[i]);
    } else if (i < t1 + t2) {
        int j = i - t1;
        ((__half*)g_W2h)[j] = __float2half(W2[j]);
    }
}

// transpose feature2: [B][D2][G] -> [B][G][D2]  (fp32)
__global__ void transpose_f2_kernel(const float* __restrict__ f2) {
    __shared__ float tile[32][33];
    int b  = blockIdx.z;
    int g0 = blockIdx.x * 32;
    int d0 = blockIdx.y * 32;
    const float* src = f2 + (size_t)b * D2 * GPTS;
    #pragma unroll
    for (int r = threadIdx.y; r < 32; r += 8)
        tile[r][threadIdx.x] = src[(size_t)(d0 + r) * GPTS + g0 + threadIdx.x];
    __syncthreads();
    float* dst = g_f2t + (size_t)b * GPTS * D2;
    #pragma unroll
    for (int r = threadIdx.y; r < 32; r += 8)
        dst[(size_t)(g0 + r) * D2 + d0 + threadIdx.x] = tile[threadIdx.x][r];
}

// transpose feature1: [B][D1][N] -> X1 rows [row][0:128] (fp16)
__global__ void transpose_f1_kernel(const float* __restrict__ f1) {
    __shared__ float tile[32][33];
    const int b  = blockIdx.z;
    const int n0 = blockIdx.x * 32;
    const int d0 = blockIdx.y * 32;
    const float* src = f1 + (size_t)b * D1 * NPTS;
    #pragma unroll
    for (int r = threadIdx.y; r < 32; r += 8)
        tile[r][threadIdx.x] = src[(size_t)(d0 + r) * NPTS + n0 + threadIdx.x];
    __syncthreads();
    __half* hi = (__half*)g_X1;
    #pragma unroll
    for (int i = threadIdx.y; i < 32; i += 8) {
        const size_t row = (size_t)b * NPTS + n0 + i;
        hi[row * CIN + d0 + threadIdx.x] = __float2half(tile[threadIdx.x][i]);
    }
}

__device__ __forceinline__ void pack8_store(const float v[8], uint4* hip) {
    uint32_t h[4];
    #pragma unroll
    for (int i = 0; i < 4; ++i) {
        __half h0 = __float2half(v[2 * i]);
        __half h1 = __float2half(v[2 * i + 1]);
        h[i] = (uint32_t)__half_as_ushort(h0) | ((uint32_t)__half_as_ushort(h1) << 16);
    }
    *hip = make_uint4(h[0], h[1], h[2], h[3]);
}

// 3-NN search only: 8 lanes x 2 points per group. Block 256 = 32 groups.
__global__ void knn_search_kernel(const float* __restrict__ coord1,
                                  const float* __restrict__ coord2) {
    __shared__ float4 s2[GPTS];
    const int b   = blockIdx.y;
    const int tid = threadIdx.x;
    const int q   = tid & 7;                        // lane within group
    const int nb  = blockIdx.x * 64 + (tid >> 3) * 2;   // first of 2 points

    const float* c2 = coord2 + (size_t)b * 3 * GPTS;
    for (int g = tid; g < GPTS; g += 256) {
        float x = c2[g], y = c2[GPTS + g], z = c2[2 * GPTS + g];
        s2[g] = make_float4(x, y, z, -0.5f * (x * x + y * y + z * z));
    }
    __syncthreads();

    const float* c1 = coord1 + (size_t)b * 3 * NPTS;
    float2 pxv = *(const float2*)(c1 + nb);
    float2 pyv = *(const float2*)(c1 + NPTS + nb);
    float2 pzv = *(const float2*)(c1 + 2 * NPTS + nb);
    const float px[2] = {pxv.x, pxv.y};
    const float py[2] = {pyv.x, pyv.y};
    const float pz[2] = {pzv.x, pzv.y};

    float e0[2], e1[2], e2[2];
    int   i0[2], i1[2], i2[2];
    #pragma unroll
    for (int p = 0; p < 2; ++p) {
        e0[p] = e1[p] = e2[p] = -CUDART_INF_F;
        i0[p] = i1[p] = i2[p] = 0;
    }

    #pragma unroll 4
    for (int it = 0; it < GPTS / 8; ++it) {
        const int g = q + it * 8;
        const float4 c = s2[g];
        #pragma unroll
        for (int p = 0; p < 2; ++p) {
            float e = fmaf(px[p], c.x, fmaf(py[p], c.y, fmaf(pz[p], c.z, c.w)));
            if (e > e2[p]) {
                if (e > e1[p]) {
                    e2[p] = e1[p]; i2[p] = i1[p];
                    if (e > e0[p]) { e1[p] = e0[p]; i1[p] = i0[p]; e0[p] = e; i0[p] = g; }
                    else           { e1[p] = e; i1[p] = g; }
                } else { e2[p] = e; i2[p] = g; }
            }
        }
    }

    #pragma unroll
    for (int off = 1; off <= 4; off <<= 1) {
        #pragma unroll
        for (int p = 0; p < 2; ++p) {
            float f0 = __shfl_xor_sync(0xffffffffu, e0[p], off);
            float f1 = __shfl_xor_sync(0xffffffffu, e1[p], off);
            float f2 = __shfl_xor_sync(0xffffffffu, e2[p], off);
            int   j0 = __shfl_xor_sync(0xffffffffu, i0[p], off);
            int   j1 = __shfl_xor_sync(0xffffffffu, i1[p], off);
            int   j2 = __shfl_xor_sync(0xffffffffu, i2[p], off);
            float m0, m1, m2; int k0, k1, k2;
            if (e0[p] >= f0) {
                m0 = e0[p]; k0 = i0[p];
                if (e1[p] >= f0) {
                    m1 = e1[p]; k1 = i1[p];
                    if (e2[p] >= f0) { m2 = e2[p]; k2 = i2[p]; } else { m2 = f0; k2 = j0; }
                } else {
                    m1 = f0; k1 = j0;
                    if (e1[p] >= f1) { m2 = e1[p]; k2 = i1[p]; } else { m2 = f1; k2 = j1; }
                }
            } else {
                m0 = f0; k0 = j0;
                if (f1 >= e0[p]) {
                    m1 = f1; k1 = j1;
                    if (f2 >= e0[p]) { m2 = f2; k2 = j2; } else { m2 = e0[p]; k2 = i0[p]; }
                } else {
                    m1 = e0[p]; k1 = i0[p];
                    if (f1 >= e1[p]) { m2 = f1; k2 = j1; } else { m2 = e1[p]; k2 = i1[p]; }
                }
            }
            e0[p] = m0; i0[p] = k0; e1[p] = m1; i1[p] = k1; e2[p] = m2; i2[p] = k2;
        }
    }

    if (q == 0) {
        #pragma unroll
        for (int p = 0; p < 2; ++p) {
            const float qn = px[p] * px[p] + py[p] * py[p] + pz[p] * pz[p];
            const float d0 = qn - 2.0f * e0[p];
            const float d1 = qn - 2.0f * e1[p];
            const float d2 = qn - 2.0f * e2[p];
            const float r0w = 1.0f / (d0 + 1e-8f);
            const float r1w = 1.0f / (d1 + 1e-8f);
            const float r2w = 1.0f / (d2 + 1e-8f);
            const float rs = 1.0f / (r0w + r1w + r2w);
            const size_t row = (size_t)b * NPTS + nb + p;
            g_knnw[row] = make_float4(r0w * rs, r1w * rs, r2w * rs, 0.f);
            g_knni[row] = make_int4(i0[p], i1[p], i2[p], 0);
        }
    }
}

// gather + interp: one warp per point; lane c handles interp chunk c (0..31).
__global__ void knn_gather_kernel() {
    const int gid = blockIdx.x * 256 + threadIdx.x;
    const size_t r = (size_t)(gid >> 5);      // point row
    const int c = gid & 31;                   // d8 chunk within D2
    const int b = (int)(r >> 12);

    const float4 w = g_knnw[r];
    const int4  ii = g_knni[r];
    const float* F = g_f2t + (size_t)b * GPTS * D2;
    const float4* p0 = (const float4*)(F + (size_t)ii.x * D2);
    const float4* p1 = (const float4*)(F + (size_t)ii.y * D2);
    const float4* p2 = (const float4*)(F + (size_t)ii.z * D2);

    float4 a0 = p0[2 * c], a1 = p0[2 * c + 1];
    float4 b0 = p1[2 * c], b1 = p1[2 * c + 1];
    float4 g0 = p2[2 * c], g1 = p2[2 * c + 1];
    float v[8];
    v[0] = w.x * a0.x + w.y * b0.x + w.z * g0.x;
    v[1] = w.x * a0.y + w.y * b0.y + w.z * g0.y;
    v[2] = w.x * a0.z + w.y * b0.z + w.z * g0.z;
    v[3] = w.x * a0.w + w.y * b0.w + w.z * g0.w;
    v[4] = w.x * a1.x + w.y * b1.x + w.z * g1.x;
    v[5] = w.x * a1.y + w.y * b1.y + w.z * g1.y;
    v[6] = w.x * a1.z + w.y * b1.z + w.z * g1.z;
    v[7] = w.x * a1.w + w.y * b1.w + w.z * g1.w;
    pack8_store(v, g_X1 + r * (CIN / 8) + D1 / 8 + c);
}

// ======================= HMMA GEMM (pure fp16, 3-stage pipeline) ============
// C[m][n] = Wh*Xh per K32 chunk. CTA tile 128(M)x128(N), 3-stage cp.async,
// one __syncthreads per chunk. 8 warps = 2(M)x4(N).
// Epilogue: fp16 n-major Yh[n][m] (raw, +bias); BN stats fused (fp32 acc).
template <int LAYER>
__global__ void __launch_bounds__(256, 2)
gemm_mma_kernel(const float* __restrict__ bias) {
    constexpr int K0 = (LAYER == 1) ? CIN : CH;
    constexpr int NC = K0 / 32;

    const __half* Wh = (LAYER == 1) ? (const __half*)g_W1h : (const __half*)g_W2h;
    const __half* Xh = (LAYER == 1) ? (const __half*)g_X1 : (const __half*)g_X2;
    __half* Yh   = (LAYER == 1) ? g_Y1h : g_Y2h;
    float* gsum  = (LAYER == 1) ? g_sum1 : g_sum2;
    float* gsq   = (LAYER == 1) ? g_sumsq1 : g_sumsq2;

    __shared__ __align__(16) __half sA[3][128 * SROW];
    __shared__ __align__(16) __half sB[3][128 * SROW];

    const int tid  = threadIdx.x;
    const int wid  = tid >> 5, lane = tid & 31;
    const int tg   = lane >> 2;            // groupID (0..7)
    const int tig  = lane & 3;             // threadID_in_group (0..3)
    const size_t r0 = (size_t)blockIdx.x * 128;   // X row block
    const int m0 = blockIdx.y * 128;              // W row block
    const int wm = (wid & 1) * 64;
    const int wn = (wid >> 1) * 32;

    const uint32_t aA = smem_u32(sA);
    const uint32_t aB = smem_u32(sB);
    const int ldr  = tid >> 2;             // load row (0..63), +64 second half
    const int ldch = tid & 3;              // 16B chunk in row (32 cols = 4)
    const uint32_t ldoff = (uint32_t)(ldr * SROW * 2 + ldch * 16);

    float acc[4][4][4];
    #pragma unroll
    for (int i = 0; i < 4; ++i)
        #pragma unroll
        for (int j = 0; j < 4; ++j)
            #pragma unroll
            for (int k = 0; k < 4; ++k) acc[i][j][k] = 0.f;

    auto issue = [&](int c, int st) {
        const int kk = c * 32;
        const uint32_t so = (uint32_t)st * TILEB + ldoff;
        #pragma unroll
        for (int i = 0; i < 2; ++i) {
            const int r = ldr + i * 64;
            const uint32_t d = so + (uint32_t)(i * 64 * SROW * 2);
            CPA16(aA + d, Wh + (size_t)(m0 + r) * K0 + kk + ldch * 8);
            CPA16(aB + d, Xh + (r0 + r) * K0 + kk + ldch * 8);
        }
        CP_COMMIT();
    };

    issue(0, 0);
    if (NC > 1) issue(1, 1);
    for (int c = 0; c < NC; ++c) {
        if (c + 1 < NC) CP_WAIT1(); else CP_WAIT0();
        __syncthreads();
        if (c + 2 < NC) issue(c + 2, (c + 2) % 3);

        const int st = c % 3;
        const __half* A = sA[st];
        const __half* B = sB[st];
        #pragma unroll
        for (int ks = 0; ks < 2; ++ks) {      // k16 steps within 32-chunk
            const int kb = ks * 16;
            int rb[4], ra0[4], ra1[4];
            #pragma unroll
            for (int ni = 0; ni < 4; ++ni) rb[ni] = (wn + ni * 8 + tg) * SROW;
            #pragma unroll
            for (int mi = 0; mi < 4; ++mi) {
                ra0[mi] = (wm + mi * 16 + tg) * SROW;
                ra1[mi] = ra0[mi] + 8 * SROW;
            }
            uint32_t bh[4][2], ah[4][4];
            #pragma unroll
            for (int ni = 0; ni < 4; ++ni) {
                bh[ni][0] = *(const uint32_t*)(&B[rb[ni] + kb + 2 * tig]);
                bh[ni][1] = *(const uint32_t*)(&B[rb[ni] + kb + 8 + 2 * tig]);
            }
            #pragma unroll
            for (int mi = 0; mi < 4; ++mi) {
                ah[mi][0] = *(const uint32_t*)(&A[ra0[mi] + kb + 2 * tig]);
                ah[mi][1] = *(const uint32_t*)(&A[ra1[mi] + kb + 2 * tig]);
                ah[mi][2] = *(const uint32_t*)(&A[ra0[mi] + kb + 8 + 2 * tig]);
                ah[mi][3] = *(const uint32_t*)(&A[ra1[mi] + kb + 8 + 2 * tig]);
            }
            #pragma unroll
            for (int mi = 0; mi < 4; ++mi)
                #pragma unroll
                for (int ni = 0; ni < 4; ++ni)
                    mma16816(acc[mi][ni], ah[mi][0], ah[mi][1], ah[mi][2], ah[mi][3],
                             bh[ni][0], bh[ni][1]);
        }
    }
    __syncthreads();

    // epilogue: fp16 store + fused BN stats (stats from fp32 accumulators)
    #pragma unroll
    for (int mi = 0; mi < 4; ++mi) {
        const int mg0 = m0 + wm + mi * 16 + tg;
        const int mg1 = mg0 + 8;
        const float bv0 = bias[mg0];
        const float bv1 = bias[mg1];
        float s0 = 0.f, q0 = 0.f, s1 = 0.f, q1 = 0.f;
        #pragma unroll
        for (int ni = 0; ni < 4; ++ni) {
            const float v00 = acc[mi][ni][0] + bv0;
            const float v01 = acc[mi][ni][1] + bv0;
            const float v10 = acc[mi][ni][2] + bv1;
            const float v11 = acc[mi][ni][3] + bv1;
            const size_t n = r0 + wn + ni * 8 + 2 * tig;
            Yh[n * 256 + mg0]       = __float2half(v00);
            Yh[(n + 1) * 256 + mg0] = __float2half(v01);
            Yh[n * 256 + mg1]       = __float2half(v10);
            Yh[(n + 1) * 256 + mg1] = __float2half(v11);
            s0 += v00 + v01; q0 += v00 * v00 + v01 * v01;
            s1 += v10 + v11; q1 += v10 * v10 + v11 * v11;
        }
        #pragma unroll
        for (int off = 1; off <= 2; off <<= 1) {
            s0 += __shfl_xor_sync(0xffffffffu, s0, off);
            q0 += __shfl_xor_sync(0xffffffffu, q0, off);
            s1 += __shfl_xor_sync(0xffffffffu, s1, off);
            q1 += __shfl_xor_sync(0xffffffffu, q1, off);
        }
        if (tig == 0) {
            atomicAdd(&gsum[mg0], s0); atomicAdd(&gsq[mg0], q0);
            atomicAdd(&gsum[mg1], s1); atomicAdd(&gsq[mg1], q1);
        }
    }
}

// ======================= finalize / fold ====================================
template <int LAYER>
__global__ void finalize_kernel(const float* __restrict__ gamma,
                                const float* __restrict__ beta) {
    const float* gsum = (LAYER == 1) ? g_sum1 : g_sum2;
    const float* gsq  = (LAYER == 1) ? g_sumsq1 : g_sumsq2;
    float* scale      = (LAYER == 1) ? g_scale1 : g_scale2;
    float* shift      = (LAYER == 1) ? g_shift1 : g_shift2;
    const int c = threadIdx.x;
    const float inv = 1.0f / (float)((size_t)NT);
    float m  = gsum[c] * inv;
    float v  = fmaxf(gsq[c] * inv - m * m, 0.f);
    float sc = gamma[c] * rsqrtf(v + BN_EPS);
    scale[c] = sc;
    shift[c] = beta[c] - m * sc;
}

// BN1 + ReLU + fp16 pack: Y1h [row][256] -> X2 [row][256]
__global__ void convert2_kernel() {
    const int gid = blockIdx.x * 256 + threadIdx.x;       // one per 8 channels
    const size_t r = (size_t)(gid >> 5);
    const int c0 = (gid & 31) * 8;
    const uint4 raw = *(const uint4*)(g_Y1h + r * 256 + c0);   // 8 halves
    const __half* hp = (const __half*)&raw;
    float4 s0 = *(const float4*)(g_scale1 + c0);
    float4 s1 = *(const float4*)(g_scale1 + c0 + 4);
    float4 t0 = *(const float4*)(g_shift1 + c0);
    float4 t1 = *(const float4*)(g_shift1 + c0 + 4);
    float v[8];
    v[0] = fmaxf(fmaf(__half2float(hp[0]), s0.x, t0.x), 0.f);
    v[1] = fmaxf(fmaf(__half2float(hp[1]), s0.y, t0.y), 0.f);
    v[2] = fmaxf(fmaf(__half2float(hp[2]), s0.z, t0.z), 0.f);
    v[3] = fmaxf(fmaf(__half2float(hp[3]), s0.w, t0.w), 0.f);
    v[4] = fmaxf(fmaf(__half2float(hp[4]), s1.x, t1.x), 0.f);
    v[5] = fmaxf(fmaf(__half2float(hp[5]), s1.y, t1.y), 0.f);
    v[6] = fmaxf(fmaf(__half2float(hp[6]), s1.z, t1.z), 0.f);
    v[7] = fmaxf(fmaf(__half2float(hp[7]), s1.w, t1.w), 0.f);
    pack8_store(v, g_X2 + (r * 256 + c0) / 8);
}

// final: Y2h [row n][m] fp16 -> out [b][m][n] fp32 with BN2 + ReLU
__global__ void transpose_out_kernel(float* __restrict__ out) {
    __shared__ float tile[32][33];
    const int r0 = blockIdx.x * 32;     // flat row (b*N + n)
    const int c0 = blockIdx.y * 32;     // channel
    #pragma unroll
    for (int i = threadIdx.y; i < 32; i += 8)
        tile[i][threadIdx.x] =
            __half2float(g_Y2h[(size_t)(r0 + i) * 256 + c0 + threadIdx.x]);
    __syncthreads();
    const int b  = r0 >> 12;
    const int n0 = r0 & (NPTS - 1);
    #pragma unroll
    for (int i = threadIdx.y; i < 32; i += 8) {
        int c = c0 + i;
        float s = g_scale2[c], t = g_shift2[c];
        out[((size_t)b * 256 + c) * NPTS + n0 + threadIdx.x] =
            fmaxf(fmaf(tile[threadIdx.x][i], s, t), 0.f);
    }
}

// ======================= launch =============================================
extern "C" void kernel_launch(void* const* d_in, const int* in_sizes, int n_in,
                              void* d_out, int out_size) {
    const float* feature1 = (const float*)d_in[0];
    const float* coord1   = (const float*)d_in[1];
    const float* feature2 = (const float*)d_in[2];
    const float* coord2   = (const float*)d_in[3];
    const float* W1 = (const float*)d_in[4];
    const float* b1 = (const float*)d_in[5];
    const float* gamma1 = (const float*)d_in[6];
    const float* beta1  = (const float*)d_in[7];
    const float* W2 = (const float*)d_in[8];
    const float* b2 = (const float*)d_in[9];
    const float* gamma2 = (const float*)d_in[10];
    const float* beta2  = (const float*)d_in[11];
    float* out = (float*)d_out;

    init_kernel<<<1, 256>>>();
    convert_w_kernel<<<(CH * CIN + COUT * CH + 255) / 256, 256>>>(W1, W2);
    transpose_f2_kernel<<<dim3(GPTS / 32, D2 / 32, BATCH), dim3(32, 8)>>>(feature2);
    transpose_f1_kernel<<<dim3(NPTS / 32, D1 / 32, BATCH), dim3(32, 8)>>>(feature1);
    knn_search_kernel<<<dim3(NPTS / 64, BATCH), 256>>>(coord1, coord2);
    knn_gather_kernel<<<NT * 32 / 256, 256>>>();

    gemm_mma_kernel<1><<<dim3(NT / 128, 2), 256>>>(b1);
    finalize_kernel<1><<<1, CH>>>(gamma1, beta1);
    convert2_kernel<<<NT * 32 / 256, 256>>>();

    gemm_mma_kernel<2><<<dim3(NT / 128, 2), 256>>>(b2);
    finalize_kernel<2><<<1, COUT>>>(gamma2, beta2);

    transpose_out_kernel<<<dim3(NT / 32, 256 / 32), dim3(32, 8)>>>(out);
}

// round 17
// speedup vs baseline: 1.0457x; 1.0457x over previous
#include <cuda_runtime.h>
#include <cuda_fp16.h>
#include <math_constants.h>
#include <cstdint>

#define BATCH 16
#define NPTS  4096
#define GPTS  1024
#define D1    128
#define D2    256
#define CIN   384
#define CH    256
#define COUT  256
#define NT    (BATCH * NPTS)      /* 65536 flat rows */
#define BN_EPS 1e-5f

#define SROW 40                    /* smem row stride in fp16 (80 B), K-chunk 32 */
#define TILEB (128 * SROW * 2)     /* one tile stage in bytes (10240) */
#define SST  136                   /* staging row stride in fp16 (272 B) */

// ======================= scratch (device globals) ===========================
__device__ uint4 g_X1[(size_t)NT * CIN / 8];     // fp16 [NT][384]
__device__ uint4 g_X2[(size_t)NT * CH / 8];      // fp16 [NT][256]
__device__ __half g_Y1h[(size_t)NT * CH];         // fp16 [NT][256] raw conv1
__device__ __half g_Y2h[(size_t)NT * COUT];       // fp16 [NT][256] raw conv2
__device__ float g_f2t[(size_t)BATCH * GPTS * D2];
__device__ float4 g_knnw[NT];                     // (w0,w1,w2,-)
__device__ int4   g_knni[NT];                     // (i0,i1,i2,-)
__device__ uint4 g_W1h[CH * CIN / 8];             // fp16 [256][384]
__device__ uint4 g_W2h[COUT * CH / 8];            // fp16 [256][256]
__device__ float g_sum1[CH],   g_sumsq1[CH];
__device__ float g_sum2[COUT], g_sumsq2[COUT];
__device__ float g_scale1[CH],   g_shift1[CH];
__device__ float g_scale2[COUT], g_shift2[COUT];

// ======================= asm helpers ========================================
__device__ __forceinline__ uint32_t smem_u32(const void* p) {
    uint32_t a;
    asm("{ .reg .u64 t; cvta.to.shared.u64 t, %1; cvt.u32.u64 %0, t; }"
        : "=r"(a) : "l"(p));
    return a;
}

#define CPA16(dst_u32, src_ptr) \
    asm volatile("cp.async.cg.shared.global [%0], [%1], 16;" \
                 :: "r"(dst_u32), "l"(src_ptr) : "memory")
#define CP_COMMIT() asm volatile("cp.async.commit_group;" ::: "memory")
#define CP_WAIT1()  asm volatile("cp.async.wait_group 1;" ::: "memory")
#define CP_WAIT0()  asm volatile("cp.async.wait_group 0;" ::: "memory")

__device__ __forceinline__ void mma16816(float c[4],
                                         uint32_t a0, uint32_t a1, uint32_t a2, uint32_t a3,
                                         uint32_t b0, uint32_t b1) {
    asm volatile(
        "mma.sync.aligned.m16n8k16.row.col.f32.f16.f16.f32 "
        "{%0,%1,%2,%3}, {%4,%5,%6,%7}, {%8,%9}, {%0,%1,%2,%3};"
        : "+f"(c[0]), "+f"(c[1]), "+f"(c[2]), "+f"(c[3])
        : "r"(a0), "r"(a1), "r"(a2), "r"(a3), "r"(b0), "r"(b1));
}

// ======================= small kernels ======================================
__global__ void init_kernel() {
    int t = threadIdx.x;
    g_sum1[t] = 0.f; g_sumsq1[t] = 0.f;
    g_sum2[t] = 0.f; g_sumsq2[t] = 0.f;
}

__global__ void convert_w_kernel(const float* __restrict__ W1,
                                 const float* __restrict__ W2) {
    int i = blockIdx.x * blockDim.x + threadIdx.x;
    const int t1 = CH * CIN;
    const int t2 = COUT * CH;
    if (i < t1) {
        ((__half*)g_W1h)[i] = __float2half(W1[i]);
    } else if (i < t1 + t2) {
        int j = i - t1;
        ((__half*)g_W2h)[j] = __float2half(W2[j]);
    }
}

// transpose feature2: [B][D2][G] -> [B][G][D2]  (fp32)
__global__ void transpose_f2_kernel(const float* __restrict__ f2) {
    __shared__ float tile[32][33];
    int b  = blockIdx.z;
    int g0 = blockIdx.x * 32;
    int d0 = blockIdx.y * 32;
    const float* src = f2 + (size_t)b * D2 * GPTS;
    #pragma unroll
    for (int r = threadIdx.y; r < 32; r += 8)
        tile[r][threadIdx.x] = src[(size_t)(d0 + r) * GPTS + g0 + threadIdx.x];
    __syncthreads();
    float* dst = g_f2t + (size_t)b * GPTS * D2;
    #pragma unroll
    for (int r = threadIdx.y; r < 32; r += 8)
        dst[(size_t)(g0 + r) * D2 + d0 + threadIdx.x] = tile[threadIdx.x][r];
}

// transpose feature1: [B][D1][N] -> X1 rows [row][0:128] (fp16)
__global__ void transpose_f1_kernel(const float* __restrict__ f1) {
    __shared__ float tile[32][33];
    const int b  = blockIdx.z;
    const int n0 = blockIdx.x * 32;
    const int d0 = blockIdx.y * 32;
    const float* src = f1 + (size_t)b * D1 * NPTS;
    #pragma unroll
    for (int r = threadIdx.y; r < 32; r += 8)
        tile[r][threadIdx.x] = src[(size_t)(d0 + r) * NPTS + n0 + threadIdx.x];
    __syncthreads();
    __half* hi = (__half*)g_X1;
    #pragma unroll
    for (int i = threadIdx.y; i < 32; i += 8) {
        const size_t row = (size_t)b * NPTS + n0 + i;
        hi[row * CIN + d0 + threadIdx.x] = __float2half(tile[threadIdx.x][i]);
    }
}

__device__ __forceinline__ void pack8_store(const float v[8], uint4* hip) {
    uint32_t h[4];
    #pragma unroll
    for (int i = 0; i < 4; ++i) {
        __half h0 = __float2half(v[2 * i]);
        __half h1 = __float2half(v[2 * i + 1]);
        h[i] = (uint32_t)__half_as_ushort(h0) | ((uint32_t)__half_as_ushort(h1) << 16);
    }
    *hip = make_uint4(h[0], h[1], h[2], h[3]);
}

// 3-NN search only: 8 lanes x 2 points per group. Block 256 = 32 groups.
__global__ void knn_search_kernel(const float* __restrict__ coord1,
                                  const float* __restrict__ coord2) {
    __shared__ float4 s2[GPTS];
    const int b   = blockIdx.y;
    const int tid = threadIdx.x;
    const int q   = tid & 7;                        // lane within group
    const int nb  = blockIdx.x * 64 + (tid >> 3) * 2;   // first of 2 points

    const float* c2 = coord2 + (size_t)b * 3 * GPTS;
    for (int g = tid; g < GPTS; g += 256) {
        float x = c2[g], y = c2[GPTS + g], z = c2[2 * GPTS + g];
        s2[g] = make_float4(x, y, z, -0.5f * (x * x + y * y + z * z));
    }
    __syncthreads();

    const float* c1 = coord1 + (size_t)b * 3 * NPTS;
    float2 pxv = *(const float2*)(c1 + nb);
    float2 pyv = *(const float2*)(c1 + NPTS + nb);
    float2 pzv = *(const float2*)(c1 + 2 * NPTS + nb);
    const float px[2] = {pxv.x, pxv.y};
    const float py[2] = {pyv.x, pyv.y};
    const float pz[2] = {pzv.x, pzv.y};

    float e0[2], e1[2], e2[2];
    int   i0[2], i1[2], i2[2];
    #pragma unroll
    for (int p = 0; p < 2; ++p) {
        e0[p] = e1[p] = e2[p] = -CUDART_INF_F;
        i0[p] = i1[p] = i2[p] = 0;
    }

    #pragma unroll 4
    for (int it = 0; it < GPTS / 8; ++it) {
        const int g = q + it * 8;
        const float4 c = s2[g];
        #pragma unroll
        for (int p = 0; p < 2; ++p) {
            float e = fmaf(px[p], c.x, fmaf(py[p], c.y, fmaf(pz[p], c.z, c.w)));
            if (e > e2[p]) {
                if (e > e1[p]) {
                    e2[p] = e1[p]; i2[p] = i1[p];
                    if (e > e0[p]) { e1[p] = e0[p]; i1[p] = i0[p]; e0[p] = e; i0[p] = g; }
                    else           { e1[p] = e; i1[p] = g; }
                } else { e2[p] = e; i2[p] = g; }
            }
        }
    }

    #pragma unroll
    for (int off = 1; off <= 4; off <<= 1) {
        #pragma unroll
        for (int p = 0; p < 2; ++p) {
            float f0 = __shfl_xor_sync(0xffffffffu, e0[p], off);
            float f1 = __shfl_xor_sync(0xffffffffu, e1[p], off);
            float f2 = __shfl_xor_sync(0xffffffffu, e2[p], off);
            int   j0 = __shfl_xor_sync(0xffffffffu, i0[p], off);
            int   j1 = __shfl_xor_sync(0xffffffffu, i1[p], off);
            int   j2 = __shfl_xor_sync(0xffffffffu, i2[p], off);
            float m0, m1, m2; int k0, k1, k2;
            if (e0[p] >= f0) {
                m0 = e0[p]; k0 = i0[p];
                if (e1[p] >= f0) {
                    m1 = e1[p]; k1 = i1[p];
                    if (e2[p] >= f0) { m2 = e2[p]; k2 = i2[p]; } else { m2 = f0; k2 = j0; }
                } else {
                    m1 = f0; k1 = j0;
                    if (e1[p] >= f1) { m2 = e1[p]; k2 = i1[p]; } else { m2 = f1; k2 = j1; }
                }
            } else {
                m0 = f0; k0 = j0;
                if (f1 >= e0[p]) {
                    m1 = f1; k1 = j1;
                    if (f2 >= e0[p]) { m2 = f2; k2 = j2; } else { m2 = e0[p]; k2 = i0[p]; }
                } else {
                    m1 = e0[p]; k1 = i0[p];
                    if (f1 >= e1[p]) { m2 = f1; k2 = j1; } else { m2 = e1[p]; k2 = i1[p]; }
                }
            }
            e0[p] = m0; i0[p] = k0; e1[p] = m1; i1[p] = k1; e2[p] = m2; i2[p] = k2;
        }
    }

    if (q == 0) {
        #pragma unroll
        for (int p = 0; p < 2; ++p) {
            const float qn = px[p] * px[p] + py[p] * py[p] + pz[p] * pz[p];
            const float d0 = qn - 2.0f * e0[p];
            const float d1 = qn - 2.0f * e1[p];
            const float d2 = qn - 2.0f * e2[p];
            const float r0w = 1.0f / (d0 + 1e-8f);
            const float r1w = 1.0f / (d1 + 1e-8f);
            const float r2w = 1.0f / (d2 + 1e-8f);
            const float rs = 1.0f / (r0w + r1w + r2w);
            const size_t row = (size_t)b * NPTS + nb + p;
            g_knnw[row] = make_float4(r0w * rs, r1w * rs, r2w * rs, 0.f);
            g_knni[row] = make_int4(i0[p], i1[p], i2[p], 0);
        }
    }
}

// gather + interp: one warp per point; lane c handles interp chunk c (0..31).
__global__ void knn_gather_kernel() {
    const int gid = blockIdx.x * 256 + threadIdx.x;
    const size_t r = (size_t)(gid >> 5);      // point row
    const int c = gid & 31;                   // d8 chunk within D2
    const int b = (int)(r >> 12);

    const float4 w = g_knnw[r];
    const int4  ii = g_knni[r];
    const float* F = g_f2t + (size_t)b * GPTS * D2;
    const float4* p0 = (const float4*)(F + (size_t)ii.x * D2);
    const float4* p1 = (const float4*)(F + (size_t)ii.y * D2);
    const float4* p2 = (const float4*)(F + (size_t)ii.z * D2);

    float4 a0 = p0[2 * c], a1 = p0[2 * c + 1];
    float4 b0 = p1[2 * c], b1 = p1[2 * c + 1];
    float4 g0 = p2[2 * c], g1 = p2[2 * c + 1];
    float v[8];
    v[0] = w.x * a0.x + w.y * b0.x + w.z * g0.x;
    v[1] = w.x * a0.y + w.y * b0.y + w.z * g0.y;
    v[2] = w.x * a0.z + w.y * b0.z + w.z * g0.z;
    v[3] = w.x * a0.w + w.y * b0.w + w.z * g0.w;
    v[4] = w.x * a1.x + w.y * b1.x + w.z * g1.x;
    v[5] = w.x * a1.y + w.y * b1.y + w.z * g1.y;
    v[6] = w.x * a1.z + w.y * b1.z + w.z * g1.z;
    v[7] = w.x * a1.w + w.y * b1.w + w.z * g1.w;
    pack8_store(v, g_X1 + r * (CIN / 8) + D1 / 8 + c);
}

// ======================= HMMA GEMM (pure fp16, 3-stage pipeline) ============
// C[m][n] = Wh*Xh per K32 chunk. CTA tile 128(M)x128(N), 3-stage cp.async,
// one __syncthreads per chunk. 8 warps = 2(M)x4(N).
// Epilogue: fp16 tile staged in smem, then fully-coalesced uint4 stores to
// Yh[n][m]; BN stats fused from the fp32 accumulators.
template <int LAYER>
__global__ void __launch_bounds__(256, 2)
gemm_mma_kernel(const float* __restrict__ bias) {
    constexpr int K0 = (LAYER == 1) ? CIN : CH;
    constexpr int NC = K0 / 32;

    const __half* Wh = (LAYER == 1) ? (const __half*)g_W1h : (const __half*)g_W2h;
    const __half* Xh = (LAYER == 1) ? (const __half*)g_X1 : (const __half*)g_X2;
    __half* Yh   = (LAYER == 1) ? g_Y1h : g_Y2h;
    float* gsum  = (LAYER == 1) ? g_sum1 : g_sum2;
    float* gsq   = (LAYER == 1) ? g_sumsq1 : g_sumsq2;

    // combined pipeline buffer: A stages [0,3*5120), B stages [3*5120, 6*5120)
    __shared__ __align__(16) __half sbuf[6 * 128 * SROW];

    const int tid  = threadIdx.x;
    const int wid  = tid >> 5, lane = tid & 31;
    const int tg   = lane >> 2;            // groupID (0..7)
    const int tig  = lane & 3;             // threadID_in_group (0..3)
    const size_t r0 = (size_t)blockIdx.x * 128;   // X row block
    const int m0 = blockIdx.y * 128;              // W row block
    const int wm = (wid & 1) * 64;
    const int wn = (wid >> 1) * 32;

    const uint32_t aS = smem_u32(sbuf);
    const int ldr  = tid >> 2;             // load row (0..63), +64 second half
    const int ldch = tid & 3;              // 16B chunk in row (32 cols = 4)
    const uint32_t ldoff = (uint32_t)(ldr * SROW * 2 + ldch * 16);

    float acc[4][4][4];
    #pragma unroll
    for (int i = 0; i < 4; ++i)
        #pragma unroll
        for (int j = 0; j < 4; ++j)
            #pragma unroll
            for (int k = 0; k < 4; ++k) acc[i][j][k] = 0.f;

    auto issue = [&](int c, int st) {
        const int kk = c * 32;
        #pragma unroll
        for (int i = 0; i < 2; ++i) {
            const int r = ldr + i * 64;
            const uint32_t d = (uint32_t)st * TILEB + ldoff
                             + (uint32_t)(i * 64 * SROW * 2);
            CPA16(aS + d, Wh + (size_t)(m0 + r) * K0 + kk + ldch * 8);
            CPA16(aS + 3 * TILEB + d, Xh + (r0 + r) * K0 + kk + ldch * 8);
        }
        CP_COMMIT();
    };

    issue(0, 0);
    if (NC > 1) issue(1, 1);
    for (int c = 0; c < NC; ++c) {
        if (c + 1 < NC) CP_WAIT1(); else CP_WAIT0();
        __syncthreads();
        if (c + 2 < NC) issue(c + 2, (c + 2) % 3);

        const int st = c % 3;
        const __half* A = sbuf + st * (128 * SROW);
        const __half* B = sbuf + (3 + st) * (128 * SROW);
        #pragma unroll
        for (int ks = 0; ks < 2; ++ks) {      // k16 steps within 32-chunk
            const int kb = ks * 16;
            int rb[4], ra0[4], ra1[4];
            #pragma unroll
            for (int ni = 0; ni < 4; ++ni) rb[ni] = (wn + ni * 8 + tg) * SROW;
            #pragma unroll
            for (int mi = 0; mi < 4; ++mi) {
                ra0[mi] = (wm + mi * 16 + tg) * SROW;
                ra1[mi] = ra0[mi] + 8 * SROW;
            }
            uint32_t bh[4][2], ah[4][4];
            #pragma unroll
            for (int ni = 0; ni < 4; ++ni) {
                bh[ni][0] = *(const uint32_t*)(&B[rb[ni] + kb + 2 * tig]);
                bh[ni][1] = *(const uint32_t*)(&B[rb[ni] + kb + 8 + 2 * tig]);
            }
            #pragma unroll
            for (int mi = 0; mi < 4; ++mi) {
                ah[mi][0] = *(const uint32_t*)(&A[ra0[mi] + kb + 2 * tig]);
                ah[mi][1] = *(const uint32_t*)(&A[ra1[mi] + kb + 2 * tig]);
                ah[mi][2] = *(const uint32_t*)(&A[ra0[mi] + kb + 8 + 2 * tig]);
                ah[mi][3] = *(const uint32_t*)(&A[ra1[mi] + kb + 8 + 2 * tig]);
            }
            #pragma unroll
            for (int mi = 0; mi < 4; ++mi)
                #pragma unroll
                for (int ni = 0; ni < 4; ++ni)
                    mma16816(acc[mi][ni], ah[mi][0], ah[mi][1], ah[mi][2], ah[mi][3],
                             bh[ni][0], bh[ni][1]);
        }
    }
    __syncthreads();

    // ---- epilogue: stage fp16 tile in smem + fused BN stats ----
    __half* stg = sbuf;                 // 128 x SST staging (34 KB < 60 KB)
    #pragma unroll
    for (int mi = 0; mi < 4; ++mi) {
        const int ml0 = wm + mi * 16 + tg;
        const int ml1 = ml0 + 8;
        const float bv0 = bias[m0 + ml0];
        const float bv1 = bias[m0 + ml1];
        float s0 = 0.f, q0 = 0.f, s1 = 0.f, q1 = 0.f;
        #pragma unroll
        for (int ni = 0; ni < 4; ++ni) {
            const int nl = wn + ni * 8 + 2 * tig;
            const float v00 = acc[mi][ni][0] + bv0;
            const float v01 = acc[mi][ni][1] + bv0;
            const float v10 = acc[mi][ni][2] + bv1;
            const float v11 = acc[mi][ni][3] + bv1;
            stg[nl * SST + ml0]       = __float2half(v00);
            stg[(nl + 1) * SST + ml0] = __float2half(v01);
            stg[nl * SST + ml1]       = __float2half(v10);
            stg[(nl + 1) * SST + ml1] = __float2half(v11);
            s0 += v00 + v01; q0 += v00 * v00 + v01 * v01;
            s1 += v10 + v11; q1 += v10 * v10 + v11 * v11;
        }
        #pragma unroll
        for (int off = 1; off <= 2; off <<= 1) {
            s0 += __shfl_xor_sync(0xffffffffu, s0, off);
            q0 += __shfl_xor_sync(0xffffffffu, q0, off);
            s1 += __shfl_xor_sync(0xffffffffu, s1, off);
            q1 += __shfl_xor_sync(0xffffffffu, q1, off);
        }
        if (tig == 0) {
            atomicAdd(&gsum[m0 + ml0], s0); atomicAdd(&gsq[m0 + ml0], q0);
            atomicAdd(&gsum[m0 + ml1], s1); atomicAdd(&gsq[m0 + ml1], q1);
        }
    }
    __syncthreads();

    // coalesced store: 128 rows x 16 uint4 (256 B contiguous per row)
    #pragma unroll
    for (int i = 0; i < 8; ++i) {
        const int flat = tid + i * 256;       // 0..2047
        const int nl = flat >> 4;             // row 0..127
        const int cl = flat & 15;             // uint4 chunk in row
        *(uint4*)(Yh + (r0 + nl) * 256 + m0 + cl * 8) =
            *(const uint4*)(stg + nl * SST + cl * 8);
    }
}

// ======================= finalize / fold ====================================
template <int LAYER>
__global__ void finalize_kernel(const float* __restrict__ gamma,
                                const float* __restrict__ beta) {
    const float* gsum = (LAYER == 1) ? g_sum1 : g_sum2;
    const float* gsq  = (LAYER == 1) ? g_sumsq1 : g_sumsq2;
    float* scale      = (LAYER == 1) ? g_scale1 : g_scale2;
    float* shift      = (LAYER == 1) ? g_shift1 : g_shift2;
    const int c = threadIdx.x;
    const float inv = 1.0f / (float)((size_t)NT);
    float m  = gsum[c] * inv;
    float v  = fmaxf(gsq[c] * inv - m * m, 0.f);
    float sc = gamma[c] * rsqrtf(v + BN_EPS);
    scale[c] = sc;
    shift[c] = beta[c] - m * sc;
}

// BN1 + ReLU + fp16 pack: Y1h [row][256] -> X2 [row][256]
__global__ void convert2_kernel() {
    const int gid = blockIdx.x * 256 + threadIdx.x;       // one per 8 channels
    const size_t r = (size_t)(gid >> 5);
    const int c0 = (gid & 31) * 8;
    const uint4 raw = *(const uint4*)(g_Y1h + r * 256 + c0);   // 8 halves
    const __half* hp = (const __half*)&raw;
    float4 s0 = *(const float4*)(g_scale1 + c0);
    float4 s1 = *(const float4*)(g_scale1 + c0 + 4);
    float4 t0 = *(const float4*)(g_shift1 + c0);
    float4 t1 = *(const float4*)(g_shift1 + c0 + 4);
    float v[8];
    v[0] = fmaxf(fmaf(__half2float(hp[0]), s0.x, t0.x), 0.f);
    v[1] = fmaxf(fmaf(__half2float(hp[1]), s0.y, t0.y), 0.f);
    v[2] = fmaxf(fmaf(__half2float(hp[2]), s0.z, t0.z), 0.f);
    v[3] = fmaxf(fmaf(__half2float(hp[3]), s0.w, t0.w), 0.f);
    v[4] = fmaxf(fmaf(__half2float(hp[4]), s1.x, t1.x), 0.f);
    v[5] = fmaxf(fmaf(__half2float(hp[5]), s1.y, t1.y), 0.f);
    v[6] = fmaxf(fmaf(__half2float(hp[6]), s1.z, t1.z), 0.f);
    v[7] = fmaxf(fmaf(__half2float(hp[7]), s1.w, t1.w), 0.f);
    pack8_store(v, g_X2 + (r * 256 + c0) / 8);
}

// final: Y2h [row n][m] fp16 -> out [b][m][n] fp32 with BN2 + ReLU
__global__ void transpose_out_kernel(float* __restrict__ out) {
    __shared__ float tile[32][33];
    const int r0 = blockIdx.x * 32;     // flat row (b*N + n)
    const int c0 = blockIdx.y * 32;     // channel
    #pragma unroll
    for (int i = threadIdx.y; i < 32; i += 8)
        tile[i][threadIdx.x] =
            __half2float(g_Y2h[(size_t)(r0 + i) * 256 + c0 + threadIdx.x]);
    __syncthreads();
    const int b  = r0 >> 12;
    const int n0 = r0 & (NPTS - 1);
    #pragma unroll
    for (int i = threadIdx.y; i < 32; i += 8) {
        int c = c0 + i;
        float s = g_scale2[c], t = g_shift2[c];
        out[((size_t)b * 256 + c) * NPTS + n0 + threadIdx.x] =
            fmaxf(fmaf(tile[threadIdx.x][i], s, t), 0.f);
    }
}

// ======================= launch =============================================
extern "C" void kernel_launch(void* const* d_in, const int* in_sizes, int n_in,
                              void* d_out, int out_size) {
    const float* feature1 = (const float*)d_in[0];
    const float* coord1   = (const float*)d_in[1];
    const float* feature2 = (const float*)d_in[2];
    const float* coord2   = (const float*)d_in[3];
    const float* W1 = (const float*)d_in[4];
    const float* b1 = (const float*)d_in[5];
    const float* gamma1 = (const float*)d_in[6];
    const float* beta1  = (const float*)d_in[7];
    const float* W2 = (const float*)d_in[8];
    const float* b2 = (const float*)d_in[9];
    const float* gamma2 = (const float*)d_in[10];
    const float* beta2  = (const float*)d_in[11];
    float* out = (float*)d_out;

    init_kernel<<<1, 256>>>();
    convert_w_kernel<<<(CH * CIN + COUT * CH + 255) / 256, 256>>>(W1, W2);
    transpose_f2_kernel<<<dim3(GPTS / 32, D2 / 32, BATCH), dim3(32, 8)>>>(feature2);
    transpose_f1_kernel<<<dim3(NPTS / 32, D1 / 32, BATCH), dim3(32, 8)>>>(feature1);
    knn_search_kernel<<<dim3(NPTS / 64, BATCH), 256>>>(coord1, coord2);
    knn_gather_kernel<<<NT * 32 / 256, 256>>>();

    gemm_mma_kernel<1><<<dim3(NT / 128, 2), 256>>>(b1);
    finalize_kernel<1><<<1, CH>>>(gamma1, beta1);
    convert2_kernel<<<NT * 32 / 256, 256>>>();

    gemm_mma_kernel<2><<<dim3(NT / 128, 2), 256>>>(b2);
    finalize_kernel<2><<<1, COUT>>>(gamma2, beta2);

    transpose_out_kernel<<<dim3(NT / 32, 256 / 32), dim3(32, 8)>>>(out);
}